// round 6
// baseline (speedup 1.0000x reference)
#include <cuda_runtime.h>
#include <cstdint>

#define NN 100000
#define NE 1600000
#define F  128

// Scratch (allocation-free rule: __device__ globals)
__device__ float g_h[(size_t)NN * F];   // h = x @ W
__device__ float g_dinv[NN];
__device__ int   g_deg[NN];
__device__ int   g_src[NE];
__device__ int   g_dst[NE];
__device__ int   g_is64;

// ------------------------------------------------- edge dtype detection ----
// int64 little-endian with values in [0, 2^31): every odd int32 word is 0.
// int32 data: odd words are random node ids -> virtually surely nonzero.
__global__ void k_detect(const int* __restrict__ ei32) {
    __shared__ int nz;
    if (threadIdx.x == 0) nz = 0;
    __syncthreads();
    for (int i = threadIdx.x; i < 8192; i += blockDim.x)
        if (ei32[2 * i + 1] != 0) nz = 1;
    __syncthreads();
    if (threadIdx.x == 0) g_is64 = (nz == 0) ? 1 : 0;
}

// Materialize src/dst as int32 regardless of input dtype.
__global__ void k_convert(const void* __restrict__ ei) {
    long long t = (long long)blockIdx.x * blockDim.x + threadIdx.x;
    if (t >= 2LL * NE) return;
    int v;
    if (g_is64) v = (int)((const long long*)ei)[t];
    else        v = ((const int*)ei)[t];
    if (t < NE) g_src[t] = v;
    else        g_dst[t - NE] = v;
}

// ---------------------------------------------------------------- degree ----
__global__ void k_deg_init() {
    int i = blockIdx.x * blockDim.x + threadIdx.x;
    if (i < NN) g_deg[i] = 1;  // self-loop
}

__global__ void k_deg_count() {
    int e = blockIdx.x * blockDim.x + threadIdx.x;
    if (e < NE) atomicAdd(&g_deg[g_dst[e]], 1);
}

__global__ void k_dinv() {
    int i = blockIdx.x * blockDim.x + threadIdx.x;
    if (i < NN) g_dinv[i] = rsqrtf((float)g_deg[i]);
}

// ------------------------------------------------------------------ GEMM ----
// h[M,128] = X[M,128] @ W[128,128], fp32. BM=64, BN=128, BK=16, 256 threads,
// 4x8 register microtile per thread.
__global__ __launch_bounds__(256) void k_gemm(const float* __restrict__ X,
                                              const float* __restrict__ W) {
    __shared__ float As[16][64];
    __shared__ float Bs[16][128];

    int tid = threadIdx.x;
    int tx = tid & 15;        // 0..15 -> col group (8 cols)
    int ty = tid >> 4;        // 0..15 -> row group (4 rows)
    int row0 = blockIdx.x * 64;

    float c[4][8];
#pragma unroll
    for (int i = 0; i < 4; i++)
#pragma unroll
        for (int j = 0; j < 8; j++) c[i][j] = 0.0f;

    int lrow = tid >> 2;          // 0..63
    int lk   = (tid & 3) * 4;     // 0,4,8,12
    bool rowok = (row0 + lrow) < NN;
    const float* xp = X + (size_t)(row0 + lrow) * F;

    for (int k0 = 0; k0 < 128; k0 += 16) {
        float4 av = rowok ? *(const float4*)(xp + k0 + lk)
                          : make_float4(0.f, 0.f, 0.f, 0.f);
        As[lk + 0][lrow] = av.x;
        As[lk + 1][lrow] = av.y;
        As[lk + 2][lrow] = av.z;
        As[lk + 3][lrow] = av.w;

#pragma unroll
        for (int r = 0; r < 2; r++) {
            int idx = tid + r * 256;       // float4 index 0..511
            int wk = idx >> 5;             // 0..15
            int wc = (idx & 31) * 4;       // 0..124
            *(float4*)&Bs[wk][wc] = *(const float4*)(W + (size_t)(k0 + wk) * F + wc);
        }
        __syncthreads();

#pragma unroll
        for (int k = 0; k < 16; k++) {
            float4 a  = *(const float4*)&As[k][ty * 4];
            float4 b0 = *(const float4*)&Bs[k][tx * 8];
            float4 b1 = *(const float4*)&Bs[k][tx * 8 + 4];
            float aa[4] = {a.x, a.y, a.z, a.w};
            float bb[8] = {b0.x, b0.y, b0.z, b0.w, b1.x, b1.y, b1.z, b1.w};
#pragma unroll
            for (int i = 0; i < 4; i++)
#pragma unroll
                for (int j = 0; j < 8; j++) c[i][j] = fmaf(aa[i], bb[j], c[i][j]);
        }
        __syncthreads();
    }

#pragma unroll
    for (int i = 0; i < 4; i++) {
        int row = row0 + ty * 4 + i;
        if (row < NN) {
            float* hp = g_h + (size_t)row * F + tx * 8;
            float4 v0 = make_float4(c[i][0], c[i][1], c[i][2], c[i][3]);
            float4 v1 = make_float4(c[i][4], c[i][5], c[i][6], c[i][7]);
            *(float4*)hp = v0;
            *(float4*)(hp + 4) = v1;
        }
    }
}

// ----------------------------------------------------- out init (self-loop) -
// out[i,f] = h[i,f] * dinv[i]^2 + b[f]
__global__ void k_init_out(float* __restrict__ out, const float* __restrict__ b) {
    int t = blockIdx.x * blockDim.x + threadIdx.x;
    if (t >= NN * (F / 4)) return;
    int node = t >> 5;      // F/4 = 32 float4 per node
    int f4   = t & 31;
    float s = g_dinv[node];
    s = s * s;
    float4 h  = ((const float4*)g_h)[(size_t)node * 32 + f4];
    float4 bv = ((const float4*)b)[f4];
    float4 o = make_float4(fmaf(h.x, s, bv.x), fmaf(h.y, s, bv.y),
                           fmaf(h.z, s, bv.z), fmaf(h.w, s, bv.w));
    ((float4*)out)[(size_t)node * 32 + f4] = o;
}

// ------------------------------------------------------------- scatter-add --
// One warp per edge: gather h[src] (512B coalesced), scale by
// dinv[src]*dinv[dst], scalar atomicAdd (REDG) into out[dst].
__global__ __launch_bounds__(256) void k_scatter(float* __restrict__ out) {
    int e = (blockIdx.x * blockDim.x + threadIdx.x) >> 5;
    if (e >= NE) return;
    int lane = threadIdx.x & 31;

    int s = g_src[e];
    int d = g_dst[e];
    float norm = g_dinv[s] * g_dinv[d];

    float4 v = ((const float4*)(g_h + (size_t)s * F))[lane];
    float* p = out + (size_t)d * F + lane * 4;
    atomicAdd(p + 0, v.x * norm);
    atomicAdd(p + 1, v.y * norm);
    atomicAdd(p + 2, v.z * norm);
    atomicAdd(p + 3, v.w * norm);
}

// ------------------------------------------------------------------ launch --
extern "C" void kernel_launch(void* const* d_in, const int* in_sizes, int n_in,
                              void* d_out, int out_size) {
    const float* x  = (const float*)d_in[0];   // [NN, F]
    const void*  ei = d_in[1];                 // [2, NE], int32 or int64
    const float* W  = (const float*)d_in[2];   // [F, F]
    const float* b  = (const float*)d_in[3];   // [F]
    float* out = (float*)d_out;                // [NN, F]

    k_detect<<<1, 256>>>((const int*)ei);
    k_convert<<<(int)((2LL * NE + 255) / 256), 256>>>(ei);

    k_deg_init<<<(NN + 255) / 256, 256>>>();
    k_deg_count<<<(NE + 255) / 256, 256>>>();
    k_dinv<<<(NN + 255) / 256, 256>>>();

    k_gemm<<<(NN + 63) / 64, 256>>>(x, W);

    k_init_out<<<(NN * (F / 4) + 255) / 256, 256>>>(out, b);

    long long threads = (long long)NE * 32;
    k_scatter<<<(int)((threads + 255) / 256), 256>>>(out);
}

// round 7
// speedup vs baseline: 2.5309x; 2.5309x over previous
#include <cuda_runtime.h>
#include <cstdint>

#define NN 100000
#define NE 1600000
#define F  128
#define SCAN_BLK 1024
#define NBLK ((NN + SCAN_BLK - 1) / SCAN_BLK)   // 98

// Scratch (allocation-free rule: __device__ globals)
__device__ float g_h[(size_t)NN * F];   // h = x @ W
__device__ float g_dinv[NN];
__device__ int   g_deg[NN];             // in-degree (edges only, no self-loop)
__device__ int   g_src[NE];
__device__ int   g_dst[NE];
__device__ int   g_rowstart[NN + 1];
__device__ int   g_cursor[NN];
__device__ int   g_csr_src[NE];
__device__ int   g_bsum[128];
__device__ int   g_is64;

// ------------------------------------------------- edge dtype detection ----
// int64 little-endian with values in [0, 2^31): every odd int32 word is 0.
__global__ void k_detect(const int* __restrict__ ei32) {
    __shared__ int nz;
    if (threadIdx.x == 0) nz = 0;
    __syncthreads();
    for (int i = threadIdx.x; i < 8192; i += blockDim.x)
        if (ei32[2 * i + 1] != 0) nz = 1;
    __syncthreads();
    if (threadIdx.x == 0) g_is64 = (nz == 0) ? 1 : 0;
}

__global__ void k_zero_deg() {
    int i = blockIdx.x * blockDim.x + threadIdx.x;
    if (i < NN) g_deg[i] = 0;
}

// Materialize src/dst as int32; count in-degree for dst on the fly.
__global__ void k_convert(const void* __restrict__ ei) {
    long long t = (long long)blockIdx.x * blockDim.x + threadIdx.x;
    if (t >= 2LL * NE) return;
    int v;
    if (g_is64) v = (int)((const long long*)ei)[t];
    else        v = ((const int*)ei)[t];
    if (t < NE) g_src[t] = v;
    else { g_dst[t - NE] = v; atomicAdd(&g_deg[v], 1); }
}

__global__ void k_dinv() {
    int i = blockIdx.x * blockDim.x + threadIdx.x;
    if (i < NN) g_dinv[i] = rsqrtf((float)(g_deg[i] + 1));  // +1 self-loop
}

// ------------------------------------------------------- exclusive scan -----
__global__ __launch_bounds__(256) void k_scan1() {
    __shared__ int sh[256];
    int t = threadIdx.x;
    int base = blockIdx.x * SCAN_BLK + t * 4;
    int v0 = 0, v1 = 0, v2 = 0, v3 = 0;
    if (base + 3 < NN) {
        int4 d = *(const int4*)&g_deg[base];
        v0 = d.x; v1 = d.y; v2 = d.z; v3 = d.w;
    } else {
        if (base + 0 < NN) v0 = g_deg[base + 0];
        if (base + 1 < NN) v1 = g_deg[base + 1];
        if (base + 2 < NN) v2 = g_deg[base + 2];
        if (base + 3 < NN) v3 = g_deg[base + 3];
    }
    int s = v0 + v1 + v2 + v3;
    sh[t] = s;
    __syncthreads();
#pragma unroll
    for (int off = 1; off < 256; off <<= 1) {
        int x = (t >= off) ? sh[t - off] : 0;
        __syncthreads();
        sh[t] += x;
        __syncthreads();
    }
    int excl = sh[t] - s;
    if (t == 255) g_bsum[blockIdx.x] = sh[255];
    if (base + 0 < NN) g_rowstart[base + 0] = excl;
    if (base + 1 < NN) g_rowstart[base + 1] = excl + v0;
    if (base + 2 < NN) g_rowstart[base + 2] = excl + v0 + v1;
    if (base + 3 < NN) g_rowstart[base + 3] = excl + v0 + v1 + v2;
}

__global__ void k_scan2() {
    __shared__ int sh[128];
    int t = threadIdx.x;  // 128 threads
    int v = (t < NBLK) ? g_bsum[t] : 0;
    sh[t] = v;
    __syncthreads();
#pragma unroll
    for (int off = 1; off < 128; off <<= 1) {
        int x = (t >= off) ? sh[t - off] : 0;
        __syncthreads();
        sh[t] += x;
        __syncthreads();
    }
    if (t < NBLK) g_bsum[t] = sh[t] - v;  // exclusive
    if (t == 0) g_rowstart[NN] = NE;
}

__global__ void k_scan3() {
    int i = blockIdx.x * blockDim.x + threadIdx.x;
    if (i < NN) {
        g_rowstart[i] += g_bsum[i / SCAN_BLK];
        g_cursor[i] = 0;
    }
}

// --------------------------------------------------------------- CSR fill ---
__global__ void k_fill() {
    int e = blockIdx.x * blockDim.x + threadIdx.x;
    if (e >= NE) return;
    int d = g_dst[e];
    int pos = g_rowstart[d] + atomicAdd(&g_cursor[d], 1);
    g_csr_src[pos] = g_src[e];
}

// ------------------------------------------------------------------ GEMM ----
// h[M,128] = X[M,128] @ W[128,128], fp32. BM=64, BN=128, BK=16, 256 threads.
__global__ __launch_bounds__(256) void k_gemm(const float* __restrict__ X,
                                              const float* __restrict__ W) {
    __shared__ float As[16][64];
    __shared__ float Bs[16][128];

    int tid = threadIdx.x;
    int tx = tid & 15;
    int ty = tid >> 4;
    int row0 = blockIdx.x * 64;

    float c[4][8];
#pragma unroll
    for (int i = 0; i < 4; i++)
#pragma unroll
        for (int j = 0; j < 8; j++) c[i][j] = 0.0f;

    int lrow = tid >> 2;
    int lk   = (tid & 3) * 4;
    bool rowok = (row0 + lrow) < NN;
    const float* xp = X + (size_t)(row0 + lrow) * F;

    for (int k0 = 0; k0 < 128; k0 += 16) {
        float4 av = rowok ? *(const float4*)(xp + k0 + lk)
                          : make_float4(0.f, 0.f, 0.f, 0.f);
        As[lk + 0][lrow] = av.x;
        As[lk + 1][lrow] = av.y;
        As[lk + 2][lrow] = av.z;
        As[lk + 3][lrow] = av.w;

#pragma unroll
        for (int r = 0; r < 2; r++) {
            int idx = tid + r * 256;
            int wk = idx >> 5;
            int wc = (idx & 31) * 4;
            *(float4*)&Bs[wk][wc] = *(const float4*)(W + (size_t)(k0 + wk) * F + wc);
        }
        __syncthreads();

#pragma unroll
        for (int k = 0; k < 16; k++) {
            float4 a  = *(const float4*)&As[k][ty * 4];
            float4 b0 = *(const float4*)&Bs[k][tx * 8];
            float4 b1 = *(const float4*)&Bs[k][tx * 8 + 4];
            float aa[4] = {a.x, a.y, a.z, a.w};
            float bb[8] = {b0.x, b0.y, b0.z, b0.w, b1.x, b1.y, b1.z, b1.w};
#pragma unroll
            for (int i = 0; i < 4; i++)
#pragma unroll
                for (int j = 0; j < 8; j++) c[i][j] = fmaf(aa[i], bb[j], c[i][j]);
        }
        __syncthreads();
    }

#pragma unroll
    for (int i = 0; i < 4; i++) {
        int row = row0 + ty * 4 + i;
        if (row < NN) {
            float* hp = g_h + (size_t)row * F + tx * 8;
            *(float4*)hp       = make_float4(c[i][0], c[i][1], c[i][2], c[i][3]);
            *(float4*)(hp + 4) = make_float4(c[i][4], c[i][5], c[i][6], c[i][7]);
        }
    }
}

// ---------------------------------------------------------------- gather ----
// One warp per destination node. acc = h[d]*dinv[d]^2 + sum_e h[src_e]*norm_e,
// out = acc + bias. Unroll by 4 for MLP; all h traffic is plain LDG in L2.
__global__ __launch_bounds__(256) void k_gather(float* __restrict__ out,
                                                const float* __restrict__ b) {
    int node = (blockIdx.x * 256 + threadIdx.x) >> 5;
    if (node >= NN) return;
    int lane = threadIdx.x & 31;

    float di = g_dinv[node];
    float4 hv = ((const float4*)(g_h + (size_t)node * F))[lane];
    float sl = di * di;
    float ax = hv.x * sl, ay = hv.y * sl, az = hv.z * sl, aw = hv.w * sl;

    int beg = g_rowstart[node];
    int end = g_rowstart[node + 1];
    int e = beg;
    for (; e + 4 <= end; e += 4) {
        int s0 = g_csr_src[e + 0];
        int s1 = g_csr_src[e + 1];
        int s2 = g_csr_src[e + 2];
        int s3 = g_csr_src[e + 3];
        float n0 = di * g_dinv[s0];
        float n1 = di * g_dinv[s1];
        float n2 = di * g_dinv[s2];
        float n3 = di * g_dinv[s3];
        float4 v0 = ((const float4*)(g_h + (size_t)s0 * F))[lane];
        float4 v1 = ((const float4*)(g_h + (size_t)s1 * F))[lane];
        float4 v2 = ((const float4*)(g_h + (size_t)s2 * F))[lane];
        float4 v3 = ((const float4*)(g_h + (size_t)s3 * F))[lane];
        ax = fmaf(v0.x, n0, fmaf(v1.x, n1, fmaf(v2.x, n2, fmaf(v3.x, n3, ax))));
        ay = fmaf(v0.y, n0, fmaf(v1.y, n1, fmaf(v2.y, n2, fmaf(v3.y, n3, ay))));
        az = fmaf(v0.z, n0, fmaf(v1.z, n1, fmaf(v2.z, n2, fmaf(v3.z, n3, az))));
        aw = fmaf(v0.w, n0, fmaf(v1.w, n1, fmaf(v2.w, n2, fmaf(v3.w, n3, aw))));
    }
    for (; e < end; e++) {
        int s = g_csr_src[e];
        float n = di * g_dinv[s];
        float4 v = ((const float4*)(g_h + (size_t)s * F))[lane];
        ax = fmaf(v.x, n, ax);
        ay = fmaf(v.y, n, ay);
        az = fmaf(v.z, n, az);
        aw = fmaf(v.w, n, aw);
    }

    float4 bv = ((const float4*)b)[lane];
    ((float4*)(out + (size_t)node * F))[lane] =
        make_float4(ax + bv.x, ay + bv.y, az + bv.z, aw + bv.w);
}

// ------------------------------------------------------------------ launch --
extern "C" void kernel_launch(void* const* d_in, const int* in_sizes, int n_in,
                              void* d_out, int out_size) {
    const float* x  = (const float*)d_in[0];   // [NN, F]
    const void*  ei = d_in[1];                 // [2, NE], int32 or int64
    const float* W  = (const float*)d_in[2];   // [F, F]
    const float* b  = (const float*)d_in[3];   // [F]
    float* out = (float*)d_out;                // [NN, F]

    k_detect<<<1, 256>>>((const int*)ei);
    k_zero_deg<<<(NN + 255) / 256, 256>>>();
    k_convert<<<(int)((2LL * NE + 255) / 256), 256>>>(ei);
    k_dinv<<<(NN + 255) / 256, 256>>>();

    k_scan1<<<NBLK, 256>>>();
    k_scan2<<<1, 128>>>();
    k_scan3<<<(NN + 255) / 256, 256>>>();
    k_fill<<<(NE + 255) / 256, 256>>>();

    k_gemm<<<(NN + 63) / 64, 256>>>(x, W);

    k_gather<<<(NN * 32 + 255) / 256, 256>>>(out, b);
}

// round 8
// speedup vs baseline: 2.8197x; 1.1141x over previous
#include <cuda_runtime.h>
#include <cstdint>

#define NN 100000
#define NE 1600000
#define F  128
#define SCAN_BLK 1024
#define NBLK ((NN + SCAN_BLK - 1) / SCAN_BLK)   // 98

// Scratch (allocation-free rule: __device__ globals)
__device__ float g_h[(size_t)NN * F];   // h = x @ W
__device__ float g_dinv[NN];
__device__ int   g_deg[NN];
__device__ int   g_src[NE];
__device__ int   g_dst[NE];
__device__ int   g_rowstart[NN + 1];
__device__ int   g_cursor[NN];
__device__ int   g_csr_src[NE];
__device__ int   g_bsum[128];
__device__ int   g_is64;

// ------------------------------------------------- edge dtype detection ----
__global__ void k_detect(const int* __restrict__ ei32) {
    __shared__ int nz;
    if (threadIdx.x == 0) nz = 0;
    __syncthreads();
    for (int i = threadIdx.x; i < 8192; i += blockDim.x)
        if (ei32[2 * i + 1] != 0) nz = 1;
    __syncthreads();
    if (threadIdx.x == 0) g_is64 = (nz == 0) ? 1 : 0;
}

__global__ void k_zero_deg() {
    int i = blockIdx.x * blockDim.x + threadIdx.x;
    if (i < NN) g_deg[i] = 0;
}

__global__ void k_convert(const void* __restrict__ ei) {
    long long t = (long long)blockIdx.x * blockDim.x + threadIdx.x;
    if (t >= 2LL * NE) return;
    int v;
    if (g_is64) v = (int)((const long long*)ei)[t];
    else        v = ((const int*)ei)[t];
    if (t < NE) g_src[t] = v;
    else { g_dst[t - NE] = v; atomicAdd(&g_deg[v], 1); }
}

__global__ void k_dinv() {
    int i = blockIdx.x * blockDim.x + threadIdx.x;
    if (i < NN) g_dinv[i] = rsqrtf((float)(g_deg[i] + 1));  // +1 self-loop
}

// ------------------------------------------------------- exclusive scan -----
__global__ __launch_bounds__(256) void k_scan1() {
    __shared__ int sh[256];
    int t = threadIdx.x;
    int base = blockIdx.x * SCAN_BLK + t * 4;
    int v0 = 0, v1 = 0, v2 = 0, v3 = 0;
    if (base + 3 < NN) {
        int4 d = *(const int4*)&g_deg[base];
        v0 = d.x; v1 = d.y; v2 = d.z; v3 = d.w;
    } else {
        if (base + 0 < NN) v0 = g_deg[base + 0];
        if (base + 1 < NN) v1 = g_deg[base + 1];
        if (base + 2 < NN) v2 = g_deg[base + 2];
        if (base + 3 < NN) v3 = g_deg[base + 3];
    }
    int s = v0 + v1 + v2 + v3;
    sh[t] = s;
    __syncthreads();
#pragma unroll
    for (int off = 1; off < 256; off <<= 1) {
        int x = (t >= off) ? sh[t - off] : 0;
        __syncthreads();
        sh[t] += x;
        __syncthreads();
    }
    int excl = sh[t] - s;
    if (t == 255) g_bsum[blockIdx.x] = sh[255];
    if (base + 0 < NN) g_rowstart[base + 0] = excl;
    if (base + 1 < NN) g_rowstart[base + 1] = excl + v0;
    if (base + 2 < NN) g_rowstart[base + 2] = excl + v0 + v1;
    if (base + 3 < NN) g_rowstart[base + 3] = excl + v0 + v1 + v2;
}

__global__ void k_scan2() {
    __shared__ int sh[128];
    int t = threadIdx.x;  // 128 threads
    int v = (t < NBLK) ? g_bsum[t] : 0;
    sh[t] = v;
    __syncthreads();
#pragma unroll
    for (int off = 1; off < 128; off <<= 1) {
        int x = (t >= off) ? sh[t - off] : 0;
        __syncthreads();
        sh[t] += x;
        __syncthreads();
    }
    if (t < NBLK) g_bsum[t] = sh[t] - v;  // exclusive
    if (t == 0) g_rowstart[NN] = NE;
}

__global__ void k_scan3() {
    int i = blockIdx.x * blockDim.x + threadIdx.x;
    if (i < NN) {
        g_rowstart[i] += g_bsum[i / SCAN_BLK];
        g_cursor[i] = 0;
    }
}

// --------------------------------------------------------------- CSR fill ---
__global__ void k_fill() {
    int e = blockIdx.x * blockDim.x + threadIdx.x;
    if (e >= NE) return;
    int d = g_dst[e];
    int pos = g_rowstart[d] + atomicAdd(&g_cursor[d], 1);
    g_csr_src[pos] = g_src[e];
}

// ------------------------------------------------------ GEMM (3x tf32 MMA) --
// h[M,128] = X[M,128] @ W[128,128]. BM=128, BN=128, BK=16, 8 warps, each warp
// does a 32x64 tile via m16n8k8 tf32 mma. Split-TF32: a_hi*b_hi + a_hi*b_lo +
// a_lo*b_hi recovers ~fp32 accuracy on the tensor pipe.
__device__ __forceinline__ uint32_t f2tf32(float x) {
    uint32_t r;
    asm("cvt.rna.tf32.f32 %0, %1;" : "=r"(r) : "f"(x));
    return r;
}

__device__ __forceinline__ void mma8(float* c, const uint32_t* a,
                                     uint32_t b0, uint32_t b1) {
    asm volatile(
        "mma.sync.aligned.m16n8k8.row.col.f32.tf32.tf32.f32 "
        "{%0,%1,%2,%3}, {%4,%5,%6,%7}, {%8,%9}, {%0,%1,%2,%3};"
        : "+f"(c[0]), "+f"(c[1]), "+f"(c[2]), "+f"(c[3])
        : "r"(a[0]), "r"(a[1]), "r"(a[2]), "r"(a[3]), "r"(b0), "r"(b1));
}

#define BK 16
#define APAD 20   // A row stride (floats): conflict-free (20*gr+gc distinct mod 32)
#define BPAD 136  // B row stride: 136 mod 32 = 8 -> (8*gc+gr) distinct mod 32

__global__ __launch_bounds__(256) void k_gemm(const float* __restrict__ X,
                                              const float* __restrict__ W) {
    __shared__ uint32_t Ah[128 * APAD], Al[128 * APAD];
    __shared__ uint32_t Bh[BK * BPAD],  Bl[BK * BPAD];

    int tid  = threadIdx.x;
    int lane = tid & 31;
    int w    = tid >> 5;       // 0..7
    int wm   = w >> 1;         // 0..3 -> 32-row strip
    int wn   = w & 1;          // 0..1 -> 64-col strip
    int gr   = lane >> 2;      // 0..7
    int gc   = lane & 3;       // 0..3
    int row0 = blockIdx.x * 128;

    float acc[2][8][4];
#pragma unroll
    for (int i = 0; i < 2; i++)
#pragma unroll
        for (int j = 0; j < 8; j++)
#pragma unroll
            for (int q = 0; q < 4; q++) acc[i][j][q] = 0.0f;

    for (int k0 = 0; k0 < 128; k0 += BK) {
        // Load A tile: 128 rows x 16 k = 512 float4, 2 per thread.
#pragma unroll
        for (int r = 0; r < 2; r++) {
            int idx = tid + r * 256;       // 0..511
            int m   = idx >> 2;            // 4 float4 per row
            int kq  = (idx & 3) * 4;
            float4 v = (row0 + m < NN)
                ? *(const float4*)(X + (size_t)(row0 + m) * F + k0 + kq)
                : make_float4(0.f, 0.f, 0.f, 0.f);
            float vv[4] = {v.x, v.y, v.z, v.w};
#pragma unroll
            for (int q = 0; q < 4; q++) {
                uint32_t hi = f2tf32(vv[q]);
                float lo = vv[q] - __uint_as_float(hi);
                Ah[m * APAD + kq + q] = hi;
                Al[m * APAD + kq + q] = f2tf32(lo);
            }
        }
        // Load B tile: 16 k x 128 n = 512 float4, 2 per thread.
#pragma unroll
        for (int r = 0; r < 2; r++) {
            int idx = tid + r * 256;
            int k   = idx >> 5;            // 32 float4 per row
            int nq  = (idx & 31) * 4;
            float4 v = *(const float4*)(W + (size_t)(k0 + k) * F + nq);
            float vv[4] = {v.x, v.y, v.z, v.w};
#pragma unroll
            for (int q = 0; q < 4; q++) {
                uint32_t hi = f2tf32(vv[q]);
                float lo = vv[q] - __uint_as_float(hi);
                Bh[k * BPAD + nq + q] = hi;
                Bl[k * BPAD + nq + q] = f2tf32(lo);
            }
        }
        __syncthreads();

#pragma unroll
        for (int ks = 0; ks < BK; ks += 8) {
            uint32_t a_hi[2][4], a_lo[2][4];
#pragma unroll
            for (int i = 0; i < 2; i++) {
                int mb = wm * 32 + i * 16;
                a_hi[i][0] = Ah[(mb + gr)     * APAD + ks + gc];
                a_hi[i][1] = Ah[(mb + gr + 8) * APAD + ks + gc];
                a_hi[i][2] = Ah[(mb + gr)     * APAD + ks + gc + 4];
                a_hi[i][3] = Ah[(mb + gr + 8) * APAD + ks + gc + 4];
                a_lo[i][0] = Al[(mb + gr)     * APAD + ks + gc];
                a_lo[i][1] = Al[(mb + gr + 8) * APAD + ks + gc];
                a_lo[i][2] = Al[(mb + gr)     * APAD + ks + gc + 4];
                a_lo[i][3] = Al[(mb + gr + 8) * APAD + ks + gc + 4];
            }
#pragma unroll
            for (int j = 0; j < 8; j++) {
                int nb = wn * 64 + j * 8;
                uint32_t bh0 = Bh[(ks + gc)     * BPAD + nb + gr];
                uint32_t bh1 = Bh[(ks + gc + 4) * BPAD + nb + gr];
                uint32_t bl0 = Bl[(ks + gc)     * BPAD + nb + gr];
                uint32_t bl1 = Bl[(ks + gc + 4) * BPAD + nb + gr];
#pragma unroll
                for (int i = 0; i < 2; i++) {
                    mma8(acc[i][j], a_hi[i], bh0, bh1);
                    mma8(acc[i][j], a_hi[i], bl0, bl1);
                    mma8(acc[i][j], a_lo[i], bh0, bh1);
                }
            }
        }
        __syncthreads();
    }

    // Epilogue: c0,c1 -> D[gr][2gc..], c2,c3 -> D[gr+8][2gc..]
#pragma unroll
    for (int i = 0; i < 2; i++) {
        int rbase = row0 + wm * 32 + i * 16;
#pragma unroll
        for (int j = 0; j < 8; j++) {
            int col = wn * 64 + j * 8 + 2 * gc;
            int r1 = rbase + gr;
            int r2 = rbase + gr + 8;
            if (r1 < NN)
                *(float2*)(g_h + (size_t)r1 * F + col) =
                    make_float2(acc[i][j][0], acc[i][j][1]);
            if (r2 < NN)
                *(float2*)(g_h + (size_t)r2 * F + col) =
                    make_float2(acc[i][j][2], acc[i][j][3]);
        }
    }
}

// ---------------------------------------------------------------- gather ----
__global__ __launch_bounds__(256) void k_gather(float* __restrict__ out,
                                                const float* __restrict__ b) {
    int node = (blockIdx.x * 256 + threadIdx.x) >> 5;
    if (node >= NN) return;
    int lane = threadIdx.x & 31;

    float di = g_dinv[node];
    float4 hv = ((const float4*)(g_h + (size_t)node * F))[lane];
    float sl = di * di;
    float ax = hv.x * sl, ay = hv.y * sl, az = hv.z * sl, aw = hv.w * sl;

    int beg = g_rowstart[node];
    int end = g_rowstart[node + 1];
    int e = beg;
    for (; e + 4 <= end; e += 4) {
        int s0 = g_csr_src[e + 0];
        int s1 = g_csr_src[e + 1];
        int s2 = g_csr_src[e + 2];
        int s3 = g_csr_src[e + 3];
        float n0 = di * g_dinv[s0];
        float n1 = di * g_dinv[s1];
        float n2 = di * g_dinv[s2];
        float n3 = di * g_dinv[s3];
        float4 v0 = ((const float4*)(g_h + (size_t)s0 * F))[lane];
        float4 v1 = ((const float4*)(g_h + (size_t)s1 * F))[lane];
        float4 v2 = ((const float4*)(g_h + (size_t)s2 * F))[lane];
        float4 v3 = ((const float4*)(g_h + (size_t)s3 * F))[lane];
        ax = fmaf(v0.x, n0, fmaf(v1.x, n1, fmaf(v2.x, n2, fmaf(v3.x, n3, ax))));
        ay = fmaf(v0.y, n0, fmaf(v1.y, n1, fmaf(v2.y, n2, fmaf(v3.y, n3, ay))));
        az = fmaf(v0.z, n0, fmaf(v1.z, n1, fmaf(v2.z, n2, fmaf(v3.z, n3, az))));
        aw = fmaf(v0.w, n0, fmaf(v1.w, n1, fmaf(v2.w, n2, fmaf(v3.w, n3, aw))));
    }
    for (; e < end; e++) {
        int s = g_csr_src[e];
        float n = di * g_dinv[s];
        float4 v = ((const float4*)(g_h + (size_t)s * F))[lane];
        ax = fmaf(v.x, n, ax);
        ay = fmaf(v.y, n, ay);
        az = fmaf(v.z, n, az);
        aw = fmaf(v.w, n, aw);
    }

    float4 bv = ((const float4*)b)[lane];
    ((float4*)(out + (size_t)node * F))[lane] =
        make_float4(ax + bv.x, ay + bv.y, az + bv.z, aw + bv.w);
}

// ------------------------------------------------------------------ launch --
extern "C" void kernel_launch(void* const* d_in, const int* in_sizes, int n_in,
                              void* d_out, int out_size) {
    const float* x  = (const float*)d_in[0];   // [NN, F]
    const void*  ei = d_in[1];                 // [2, NE], int32 or int64
    const float* W  = (const float*)d_in[2];   // [F, F]
    const float* b  = (const float*)d_in[3];   // [F]
    float* out = (float*)d_out;                // [NN, F]

    k_detect<<<1, 256>>>((const int*)ei);
    k_zero_deg<<<(NN + 255) / 256, 256>>>();
    k_convert<<<(int)((2LL * NE + 255) / 256), 256>>>(ei);
    k_dinv<<<(NN + 255) / 256, 256>>>();

    k_scan1<<<NBLK, 256>>>();
    k_scan2<<<1, 128>>>();
    k_scan3<<<(NN + 255) / 256, 256>>>();
    k_fill<<<(NE + 255) / 256, 256>>>();

    k_gemm<<<(NN + 127) / 128, 256>>>(x, W);

    k_gather<<<(NN * 32 + 255) / 256, 256>>>(out, b);
}